// round 2
// baseline (speedup 1.0000x reference)
#include <cuda_runtime.h>
#include <math.h>

#define N_NODES 200000
#define N_DEST  8192
#define N_EDGE  262144
#define D_MEM   128
#define D_FEAT  128
#define D_EDGE  64
#define D_TIME  32
#define D_READ  128
#define D_MSG   128

// ---------------- scratch (device globals: allocation-free) ----------------
__device__ float g_msg_sum[N_DEST * D_MSG];
__device__ float g_cnt[N_DEST];
__device__ int   g_idx64;

// ---------------- index-width probe -----------------------------------------
__global__ void probe_kernel(const unsigned int* __restrict__ w) {
    g_idx64 = (w[1] == 0u && w[3] == 0u) ? 1 : 0;
}

__device__ __forceinline__ int idx_at(const void* p, long long i, int is64) {
    return is64 ? (int)((const long long*)p)[i] : ((const int*)p)[i];
}

// ---------------- tf32 helpers ----------------------------------------------
__device__ __forceinline__ unsigned f2tf(float x) {
    unsigned r;
    asm("cvt.rna.tf32.f32 %0, %1;" : "=r"(r) : "f"(x));
    return r;
}
__device__ __forceinline__ void split_tf32(float x, unsigned& hi, unsigned& lo) {
    hi = f2tf(x);
    float res = x - __uint_as_float(hi);
    lo = f2tf(res);
}
__device__ __forceinline__ void mma_tf32(float* c, const unsigned* a, const unsigned* b) {
    asm volatile(
        "mma.sync.aligned.m16n8k8.row.col.f32.tf32.tf32.f32 "
        "{%0,%1,%2,%3},{%4,%5,%6,%7},{%8,%9},{%0,%1,%2,%3};"
        : "+f"(c[0]), "+f"(c[1]), "+f"(c[2]), "+f"(c[3])
        : "r"(a[0]), "r"(a[1]), "r"(a[2]), "r"(a[3]), "r"(b[0]), "r"(b[1]));
}

// ---------------- edge kernel (tensor-core 3xTF32) ---------------------------
#define MT 128
#define STG 228
#define SA_STRIDE 36
#define SW_STRIDE 136
#define STAGE_FLOATS (128 * STG)      // 29184
#define SA_FLOATS (128 * SA_STRIDE)   // 4608
#define SW_FLOATS (32 * SW_STRIDE)    // 4352
#define EDGE_SMEM ((STAGE_FLOATS + SA_FLOATS + SW_FLOATS) * 4)

// One 32-K chunk of warp-level mma over A [rows][strideA] and B smem [32][SW_STRIDE].
// Warp computes rows [arow0, arow0+32) x cols [bcol0, bcol0+64) in acc[2][8][4].
__device__ __forceinline__ void mma_tile(const float* __restrict__ A, int strideA,
                                         int arow0, const float* __restrict__ B,
                                         int bcol0, int gid, int tig,
                                         float acc[2][8][4]) {
#pragma unroll
    for (int ks = 0; ks < 4; ks++) {
        const int k0 = ks * 8;
        unsigned ah[2][4], al[2][4];
#pragma unroll
        for (int mf = 0; mf < 2; mf++) {
            const float* ap = A + (arow0 + mf * 16 + gid) * strideA + k0 + tig;
            split_tf32(ap[0], ah[mf][0], al[mf][0]);                 // (gid, tig)
            split_tf32(ap[8 * strideA], ah[mf][1], al[mf][1]);       // (gid+8, tig)
            split_tf32(ap[4], ah[mf][2], al[mf][2]);                 // (gid, tig+4)
            split_tf32(ap[8 * strideA + 4], ah[mf][3], al[mf][3]);   // (gid+8, tig+4)
        }
        unsigned bh[8][2], bl[8][2];
#pragma unroll
        for (int nf = 0; nf < 8; nf++) {
            const int col = bcol0 + nf * 8 + gid;
            split_tf32(B[(k0 + tig) * SW_STRIDE + col], bh[nf][0], bl[nf][0]);
            split_tf32(B[(k0 + tig + 4) * SW_STRIDE + col], bh[nf][1], bl[nf][1]);
        }
#pragma unroll
        for (int mf = 0; mf < 2; mf++)
#pragma unroll
            for (int nf = 0; nf < 8; nf++) {
                mma_tf32(acc[mf][nf], ah[mf], bh[nf]);
                mma_tf32(acc[mf][nf], ah[mf], bl[nf]);
                mma_tf32(acc[mf][nf], al[mf], bh[nf]);
            }
    }
}

__device__ __forceinline__ void zero_acc8(float acc[2][8][4]) {
#pragma unroll
    for (int m = 0; m < 2; m++)
#pragma unroll
        for (int n = 0; n < 8; n++)
#pragma unroll
            for (int c = 0; c < 4; c++) acc[m][n][c] = 0.f;
}

__device__ __forceinline__ void flush_seg(int d, int tx, const float* r, float rl) {
    float* p = g_msg_sum + (size_t)d * D_MSG + tx * 4;
    atomicAdd(p + 0, r[0]);
    atomicAdd(p + 1, r[1]);
    atomicAdd(p + 2, r[2]);
    atomicAdd(p + 3, r[3]);
    if (tx == 0) atomicAdd(&g_cnt[d], rl);
}

__global__ __launch_bounds__(256) void edge_kernel(
    const float* __restrict__ node_memory, const float* __restrict__ node_features,
    const float* __restrict__ edge_features, const float* __restrict__ time_encoding,
    const void* __restrict__ source_ids, const void* __restrict__ edge_ids,
    const void* __restrict__ dest_seg,
    const float* __restrict__ W_read, const float* __restrict__ b_read,
    const float* __restrict__ W_msg, const float* __restrict__ b_msg) {
    extern __shared__ float sm[];
    float* stage = sm;                       // [128][228]
    float* sA = sm + STAGE_FLOATS;           // [128][36]
    float* sW = sm + STAGE_FLOATS + SA_FLOATS;  // [32][136]
    __shared__ int s_src[MT], s_eid[MT], s_dst[MT];

    const int tid = threadIdx.x;
    const int lane = tid & 31;
    const int warp = tid >> 5;
    const int gid = lane >> 2;   // 0..7
    const int tig = lane & 3;    // 0..3
    const int mw = warp >> 1;    // 0..3: rows mw*32
    const int nw = warp & 1;     // 0..1: cols nw*64
    const long long ebase = (long long)blockIdx.x * MT;
    const int is64 = g_idx64;

    if (tid < MT) {
        s_src[tid] = idx_at(source_ids, ebase + tid, is64);
        s_eid[tid] = idx_at(edge_ids, ebase + tid, is64);
        s_dst[tid] = idx_at(dest_seg, ebase + tid, is64);
    }
    __syncthreads();

    // Prefill stage cols [128,192)=edge feats, [192,224)=time (2 threads/edge).
    {
        const int e = tid >> 1, q = tid & 1;
        const float4* ef = (const float4*)(edge_features + (size_t)s_eid[e] * D_EDGE) + q * 8;
        float4* de = (float4*)(stage + e * STG + 128 + q * 32);
#pragma unroll
        for (int j = 0; j < 8; j++) de[j] = ef[j];
        const float4* tf = (const float4*)(time_encoding + (ebase + e) * D_TIME) + q * 4;
        float4* dt = (float4*)(stage + e * STG + 192 + q * 16);
#pragma unroll
        for (int j = 0; j < 4; j++) dt[j] = tf[j];
    }

    float acc[2][8][4];
    zero_acc8(acc);

    // ---- Phase 1: src_read = relu([mem|feat] @ W_read + b), K=256 ----
    for (int kc = 0; kc < 8; kc++) {
        __syncthreads();
        {   // gather A chunk [128][32] -> sA
            const int e = tid >> 1, q = tid & 1;
            const float* base = (kc < 4)
                ? node_memory + (size_t)s_src[e] * D_MEM + kc * 32
                : node_features + (size_t)s_src[e] * D_FEAT + (kc - 4) * 32;
            const float4* src = (const float4*)base + q * 4;
            float4* dst = (float4*)(sA + e * SA_STRIDE + q * 16);
#pragma unroll
            for (int j = 0; j < 4; j++) dst[j] = src[j];
        }
        {   // load W chunk [32][128] -> sW
            const int r = tid >> 3, c0 = (tid & 7) * 16;
            const float4* src = (const float4*)(W_read + kc * 32 * 128 + r * 128 + c0);
            float4* dst = (float4*)(sW + r * SW_STRIDE + c0);
#pragma unroll
            for (int j = 0; j < 4; j++) dst[j] = src[j];
        }
        __syncthreads();
        mma_tile(sA, SA_STRIDE, mw * 32, sW, nw * 64, gid, tig, acc);
    }

    // epilogue: bias+relu -> stage cols [0,128)
    {
        const int r0 = mw * 32, c0 = nw * 64;
#pragma unroll
        for (int mf = 0; mf < 2; mf++)
#pragma unroll
            for (int nf = 0; nf < 8; nf++) {
                const int col = c0 + nf * 8 + 2 * tig;
                const float b0 = b_read[col], b1 = b_read[col + 1];
                const int ra = r0 + mf * 16 + gid;
                stage[ra * STG + col]           = fmaxf(acc[mf][nf][0] + b0, 0.f);
                stage[ra * STG + col + 1]       = fmaxf(acc[mf][nf][1] + b1, 0.f);
                stage[(ra + 8) * STG + col]     = fmaxf(acc[mf][nf][2] + b0, 0.f);
                stage[(ra + 8) * STG + col + 1] = fmaxf(acc[mf][nf][3] + b1, 0.f);
            }
    }

    // ---- Phase 2: msgs = relu([src_read|ef|time] @ W_msg + b), K=224 ----
    zero_acc8(acc);
    for (int kc = 0; kc < 7; kc++) {
        __syncthreads();
        {   // load W_msg chunk
            const int r = tid >> 3, c0 = (tid & 7) * 16;
            const float4* src = (const float4*)(W_msg + kc * 32 * 128 + r * 128 + c0);
            float4* dst = (float4*)(sW + r * SW_STRIDE + c0);
#pragma unroll
            for (int j = 0; j < 4; j++) dst[j] = src[j];
        }
        __syncthreads();
        mma_tile(stage + kc * 32, STG, mw * 32, sW, nw * 64, gid, tig, acc);
    }

    // epilogue: bias+relu msgs -> stage cols [0,128)
    // Safe: all warps are past the top-of-kc=6 barrier, so remaining reads
    // touch only cols [192,224).
    {
        const int r0 = mw * 32, c0 = nw * 64;
#pragma unroll
        for (int mf = 0; mf < 2; mf++)
#pragma unroll
            for (int nf = 0; nf < 8; nf++) {
                const int col = c0 + nf * 8 + 2 * tig;
                const float b0 = b_msg[col], b1 = b_msg[col + 1];
                const int ra = r0 + mf * 16 + gid;
                stage[ra * STG + col]           = fmaxf(acc[mf][nf][0] + b0, 0.f);
                stage[ra * STG + col + 1]       = fmaxf(acc[mf][nf][1] + b1, 0.f);
                stage[(ra + 8) * STG + col]     = fmaxf(acc[mf][nf][2] + b0, 0.f);
                stage[(ra + 8) * STG + col + 1] = fmaxf(acc[mf][nf][3] + b1, 0.f);
            }
    }
    __syncthreads();

    // ---- Phase 3: run-coalesced segment-sum atomics (dest_seg sorted) ----
    {
        const int tx = tid & 31;      // 4 cols
        const int gR = tid >> 5;      // 8 groups x 16 edges
        const int e0 = gR * 16;
        int curd = s_dst[e0];
        float r[4] = {0.f, 0.f, 0.f, 0.f};
        float rl = 0.f;
#pragma unroll
        for (int i = 0; i < 16; i++) {
            const int e = e0 + i;
            const int d = s_dst[e];
            const float4 v = *(const float4*)(stage + e * STG + tx * 4);
            if (d != curd) {
                flush_seg(curd, tx, r, rl);
                curd = d;
                r[0] = r[1] = r[2] = r[3] = 0.f;
                rl = 0.f;
            }
            r[0] += v.x; r[1] += v.y; r[2] += v.z; r[3] += v.w;
            rl += 1.f;
        }
        flush_seg(curd, tx, r, rl);
    }
}

// ---------------- dest pipeline (fp32, unchanged from R1) --------------------
#define TILE_E 64

__device__ __forceinline__ void mma_chunk(const float* __restrict__ Asub, int strideA,
                                          const float* __restrict__ Ws,
                                          int ty, int tx, float acc[8][4]) {
#pragma unroll
    for (int k = 0; k < 32; k++) {
        const float* arow = Asub + k * strideA + ty * 8;
        float4 a0 = *(const float4*)(arow);
        float4 a1 = *(const float4*)(arow + 4);
        float4 w  = *(const float4*)(Ws + k * 128 + tx * 4);
        float av[8] = {a0.x, a0.y, a0.z, a0.w, a1.x, a1.y, a1.z, a1.w};
#pragma unroll
        for (int i = 0; i < 8; i++) {
            acc[i][0] = fmaf(av[i], w.x, acc[i][0]);
            acc[i][1] = fmaf(av[i], w.y, acc[i][1]);
            acc[i][2] = fmaf(av[i], w.z, acc[i][2]);
            acc[i][3] = fmaf(av[i], w.w, acc[i][3]);
        }
    }
}

__device__ __forceinline__ void load_w(float* Ws, const float* __restrict__ Wsrc, int tid) {
    const float4* s = (const float4*)Wsrc;
    float4* d = (float4*)Ws;
#pragma unroll
    for (int i = 0; i < 4; i++) d[tid + i * 256] = s[tid + i * 256];
}

__device__ __forceinline__ void zero_acc(float acc[8][4]) {
#pragma unroll
    for (int i = 0; i < 8; i++)
#pragma unroll
        for (int c = 0; c < 4; c++) acc[i][c] = 0.f;
}

__global__ __launch_bounds__(256) void dest_kernel(
    const float* __restrict__ node_memory, const float* __restrict__ node_features,
    const void* __restrict__ node_ids,
    const float* __restrict__ W_read, const float* __restrict__ b_read,
    const float* __restrict__ W_agg, const float* __restrict__ b_agg,
    const float* __restrict__ W_upd, const float* __restrict__ b_upd,
    const float* __restrict__ W_write, const float* __restrict__ b_write,
    float* __restrict__ out) {
    extern __shared__ float sm[];
    float* As = sm;             // [32][64]
    float* Ws = sm + 2048;      // [32][128]
    float* CT = sm + 6144;      // [256][68]
    float* DR = sm + 23552;     // [128][68]
    __shared__ int s_nid[TILE_E];

    const int tid = threadIdx.x;
    const int tx = tid & 31;
    const int ty = tid >> 5;
    const int eL = tid & 63;
    const int kq = tid >> 6;
    const int rbase = blockIdx.x * TILE_E;
    const int is64 = g_idx64;

    if (tid < TILE_E) s_nid[tid] = idx_at(node_ids, rbase + tid, is64);

    float acc[8][4];
    zero_acc(acc);

    for (int kc = 0; kc < 8; kc++) {
        __syncthreads();
        {
            const float* row = (kc < 4)
                ? node_memory + (size_t)s_nid[eL] * D_MEM + kc * 32
                : node_features + (size_t)s_nid[eL] * D_FEAT + (kc - 4) * 32;
            float4 v0 = ((const float4*)row)[kq * 2];
            float4 v1 = ((const float4*)row)[kq * 2 + 1];
            int kb = kq * 8;
            As[(kb + 0) * 64 + eL] = v0.x; As[(kb + 1) * 64 + eL] = v0.y;
            As[(kb + 2) * 64 + eL] = v0.z; As[(kb + 3) * 64 + eL] = v0.w;
            As[(kb + 4) * 64 + eL] = v1.x; As[(kb + 5) * 64 + eL] = v1.y;
            As[(kb + 6) * 64 + eL] = v1.z; As[(kb + 7) * 64 + eL] = v1.w;
        }
        load_w(Ws, W_read + kc * 32 * 128, tid);
        __syncthreads();
        mma_chunk(As, 64, Ws, ty, tx, acc);
    }
    {
        float4 bb = *(const float4*)&b_read[tx * 4];
        __syncthreads();
#pragma unroll
        for (int i = 0; i < 8; i++) {
            int e = ty * 8 + i;
#pragma unroll
            for (int c = 0; c < 4; c++) {
                float bv = (c == 0) ? bb.x : (c == 1) ? bb.y : (c == 2) ? bb.z : bb.w;
                float v = fmaxf(acc[i][c] + bv, 0.f);
                CT[(tx * 4 + c) * 68 + e] = v;
                DR[(tx * 4 + c) * 68 + e] = v;
            }
        }
    }
    {
        int dg = rbase + eL;
        float inv = 1.0f / fmaxf(g_cnt[dg], 1.0f);
        const float4* srcp = (const float4*)(g_msg_sum + (size_t)dg * D_MSG + kq * 32);
#pragma unroll
        for (int j4 = 0; j4 < 8; j4++) {
            float4 v = srcp[j4];
            int kk = 128 + kq * 32 + j4 * 4;
            CT[(kk + 0) * 68 + eL] = v.x * inv; CT[(kk + 1) * 68 + eL] = v.y * inv;
            CT[(kk + 2) * 68 + eL] = v.z * inv; CT[(kk + 3) * 68 + eL] = v.w * inv;
        }
    }

    zero_acc(acc);
    for (int kc = 0; kc < 8; kc++) {
        __syncthreads();
        load_w(Ws, W_agg + kc * 32 * 128, tid);
        __syncthreads();
        mma_chunk(CT + kc * 32 * 68, 68, Ws, ty, tx, acc);
    }
    __syncthreads();
    {
        float4 ba = *(const float4*)&b_agg[tx * 4];
#pragma unroll
        for (int i = 0; i < 8; i++) {
            int e = ty * 8 + i;
            CT[(tx * 4 + 0) * 68 + e] = fmaxf(acc[i][0] + ba.x, 0.f);
            CT[(tx * 4 + 1) * 68 + e] = fmaxf(acc[i][1] + ba.y, 0.f);
            CT[(tx * 4 + 2) * 68 + e] = fmaxf(acc[i][2] + ba.z, 0.f);
            CT[(tx * 4 + 3) * 68 + e] = fmaxf(acc[i][3] + ba.w, 0.f);
        }
#pragma unroll
        for (int j = 0; j < 32; j++) {
            int row = kq * 32 + j;
            CT[(128 + row) * 68 + eL] = DR[row * 68 + eL];
        }
    }

    zero_acc(acc);
    for (int kc = 0; kc < 8; kc++) {
        __syncthreads();
        load_w(Ws, W_upd + kc * 32 * 128, tid);
        __syncthreads();
        mma_chunk(CT + kc * 32 * 68, 68, Ws, ty, tx, acc);
    }
    __syncthreads();
    {
        float4 bu = *(const float4*)&b_upd[tx * 4];
#pragma unroll
        for (int i = 0; i < 8; i++) {
            int e = ty * 8 + i;
            DR[(tx * 4 + 0) * 68 + e] = fmaxf(acc[i][0] + bu.x, 0.f);
            DR[(tx * 4 + 1) * 68 + e] = fmaxf(acc[i][1] + bu.y, 0.f);
            DR[(tx * 4 + 2) * 68 + e] = fmaxf(acc[i][2] + bu.z, 0.f);
            DR[(tx * 4 + 3) * 68 + e] = fmaxf(acc[i][3] + bu.w, 0.f);
        }
    }

    zero_acc(acc);
    for (int kc = 0; kc < 4; kc++) {
        __syncthreads();
        load_w(Ws, W_write + kc * 32 * 128, tid);
        __syncthreads();
        mma_chunk(DR + kc * 32 * 68, 68, Ws, ty, tx, acc);
    }
    {
        float4 bw = *(const float4*)&b_write[tx * 4];
#pragma unroll
        for (int i = 0; i < 8; i++) {
            int e = ty * 8 + i;
            float4 o;
            o.x = tanhf(acc[i][0] + bw.x);
            o.y = tanhf(acc[i][1] + bw.y);
            o.z = tanhf(acc[i][2] + bw.z);
            o.w = tanhf(acc[i][3] + bw.w);
            *(float4*)(out + (size_t)s_nid[e] * D_MEM + tx * 4) = o;
        }
    }
}

// ---------------- launch ------------------------------------------------------
#define DEST_SMEM ((2048 + 4096 + 256 * 68 + 128 * 68) * 4)

extern "C" void kernel_launch(void* const* d_in, const int* in_sizes, int n_in,
                              void* d_out, int out_size) {
    const float* node_memory   = (const float*)d_in[0];
    const float* node_features = (const float*)d_in[1];
    const float* edge_features = (const float*)d_in[2];
    const float* time_encoding = (const float*)d_in[3];
    const void*  node_ids      = d_in[4];
    const void*  source_ids    = d_in[5];
    const void*  edge_ids      = d_in[6];
    const void*  dest_seg      = d_in[7];
    const float* W_read  = (const float*)d_in[8];
    const float* b_read  = (const float*)d_in[9];
    const float* W_msg   = (const float*)d_in[10];
    const float* b_msg   = (const float*)d_in[11];
    const float* W_agg   = (const float*)d_in[12];
    const float* b_agg   = (const float*)d_in[13];
    const float* W_upd   = (const float*)d_in[14];
    const float* b_upd   = (const float*)d_in[15];
    const float* W_write = (const float*)d_in[16];
    const float* b_write = (const float*)d_in[17];
    float* out = (float*)d_out;

    cudaFuncSetAttribute(edge_kernel, cudaFuncAttributeMaxDynamicSharedMemorySize, EDGE_SMEM);
    cudaFuncSetAttribute(dest_kernel, cudaFuncAttributeMaxDynamicSharedMemorySize, DEST_SMEM);

    void* sumP = nullptr;
    void* cntP = nullptr;
    cudaGetSymbolAddress(&sumP, g_msg_sum);
    cudaGetSymbolAddress(&cntP, g_cnt);

    probe_kernel<<<1, 1>>>((const unsigned int*)d_in[4]);
    cudaMemsetAsync(sumP, 0, sizeof(float) * N_DEST * D_MSG);
    cudaMemsetAsync(cntP, 0, sizeof(float) * N_DEST);
    cudaMemcpyAsync(d_out, d_in[0], (size_t)N_NODES * D_MEM * sizeof(float),
                    cudaMemcpyDeviceToDevice);

    edge_kernel<<<N_EDGE / MT, 256, EDGE_SMEM>>>(
        node_memory, node_features, edge_features, time_encoding,
        source_ids, edge_ids, dest_seg, W_read, b_read, W_msg, b_msg);

    dest_kernel<<<N_DEST / TILE_E, 256, DEST_SMEM>>>(
        node_memory, node_features, node_ids,
        W_read, b_read, W_agg, b_agg, W_upd, b_upd, W_write, b_write, out);
}

// round 3
// speedup vs baseline: 2.1633x; 2.1633x over previous
#include <cuda_runtime.h>
#include <cuda_bf16.h>
#include <math.h>

#define N_NODES 200000
#define N_DEST  8192
#define N_EDGE  262144
#define D_MEM   128
#define D_FEAT  128
#define D_EDGE  64
#define D_TIME  32
#define D_MSG   128

// ---------------- scratch (device globals: allocation-free) ------------------
__device__ float g_msg_sum[N_DEST * D_MSG];   // zero-init; dest_kernel re-zeroes
__device__ float g_cnt[N_DEST];

__device__ __forceinline__ int idx_at(const void* p, long long i, int is64) {
    return is64 ? (int)((const long long*)p)[i] : ((const int*)p)[i];
}

// ---------------- bf16 split-pack helpers ------------------------------------
// pack (x0,x1) -> bf16x2 hi (rn) and bf16x2 lo (residual), lo half = x0.
__device__ __forceinline__ void splitpack(float x0, float x1, unsigned& hi, unsigned& lo) {
    unsigned h;
    asm("cvt.rn.bf16x2.f32 %0, %1, %2;" : "=r"(h) : "f"(x1), "f"(x0));
    float h0 = __uint_as_float(h << 16);
    float h1 = __uint_as_float(h & 0xFFFF0000u);
    float r0 = x0 - h0;
    float r1 = x1 - h1;
    unsigned l;
    asm("cvt.rn.bf16x2.f32 %0, %1, %2;" : "=r"(l) : "f"(r1), "f"(r0));
    hi = h;
    lo = l;
}

__device__ __forceinline__ void mma_bf16(float* c, const unsigned* a, const unsigned* b) {
    asm volatile(
        "mma.sync.aligned.m16n8k16.row.col.f32.bf16.bf16.f32 "
        "{%0,%1,%2,%3},{%4,%5,%6,%7},{%8,%9},{%0,%1,%2,%3};"
        : "+f"(c[0]), "+f"(c[1]), "+f"(c[2]), "+f"(c[3])
        : "r"(a[0]), "r"(a[1]), "r"(a[2]), "r"(a[3]), "r"(b[0]), "r"(b[1]));
}

// ---------------- edge kernel layout ------------------------------------------
// smem (u32 units):
#define STRIDE_A 20     // A chunk: [128 rows][16 kpairs] pad->20 (20 mod 32 = 20; 20*gid distinct)
#define STRIDE_W 136    // W chunk: [16 kpairs][128 cols] pad->136 (8 mod 32)
#define STRIDE_S 116    // stage:   [128 rows][112 kpairs] pad->116 (4 mod 32)
#define STRIDE_M 132    // msgbuf fp32 [128][128] pad->132

#define OFF_AH 0
#define OFF_AL 2560
#define OFF_WH 5120
#define OFF_WL 7296
#define OFF_SH 9472
#define OFF_SL 24320
#define EDGE_U32 39168
#define EDGE_SMEM (EDGE_U32 * 4)

__device__ __forceinline__ void flush_seg(int d, int tx, const float* r, float rl) {
    float* p = g_msg_sum + (size_t)d * D_MSG + tx * 4;
    atomicAdd(p + 0, r[0]);
    atomicAdd(p + 1, r[1]);
    atomicAdd(p + 2, r[2]);
    atomicAdd(p + 3, r[3]);
    if (tx == 0) atomicAdd(&g_cnt[d], rl);
}

__global__ __launch_bounds__(512, 1) void edge_kernel(
    const float* __restrict__ node_memory, const float* __restrict__ node_features,
    const float* __restrict__ edge_features, const float* __restrict__ time_encoding,
    const void* __restrict__ node_ids,
    const void* __restrict__ source_ids, const void* __restrict__ edge_ids,
    const void* __restrict__ dest_seg,
    const float* __restrict__ W_read, const float* __restrict__ b_read,
    const float* __restrict__ W_msg, const float* __restrict__ b_msg) {
    extern __shared__ unsigned su[];
    unsigned* sAh = su + OFF_AH;
    unsigned* sAl = su + OFF_AL;
    unsigned* sWh = su + OFF_WH;
    unsigned* sWl = su + OFF_WL;
    unsigned* sSh = su + OFF_SH;
    unsigned* sSl = su + OFF_SL;
    __shared__ int s_src[128], s_eid[128], s_dst[128];

    const int tid = threadIdx.x;
    const int lane = tid & 31;
    const int warp = tid >> 5;
    const int gid = lane >> 2;
    const int tig = lane & 3;
    const int r0 = (warp >> 2) * 32;   // row base of warp tile
    const int c0 = (warp & 3) * 32;    // col base of warp tile
    const long long ebase = (long long)blockIdx.x * 128;

    // inline index-width detect: node_ids = arange -> int64 iff words 1,3 == 0
    const unsigned* nw = (const unsigned*)node_ids;
    const int is64 = (nw[1] == 0u && nw[3] == 0u);

    if (tid < 128) {
        s_src[tid] = idx_at(source_ids, ebase + tid, is64);
        s_eid[tid] = idx_at(edge_ids, ebase + tid, is64);
        s_dst[tid] = idx_at(dest_seg, ebase + tid, is64);
    }
    __syncthreads();

    // ---- prefill stage kpairs [64,112): edge feats (64..95), time (96..111) ----
    {
        const int row = tid >> 2, q = tid & 3;
        const float4* ef = (const float4*)(edge_features + (size_t)s_eid[row] * D_EDGE);
#pragma unroll
        for (int j = 0; j < 4; j++) {
            float4 v = ef[q * 4 + j];
            unsigned h0, l0, h1, l1;
            splitpack(v.x, v.y, h0, l0);
            splitpack(v.z, v.w, h1, l1);
            const int pi = 64 + q * 8 + 2 * j;
            sSh[row * STRIDE_S + pi] = h0;     sSl[row * STRIDE_S + pi] = l0;
            sSh[row * STRIDE_S + pi + 1] = h1; sSl[row * STRIDE_S + pi + 1] = l1;
        }
        const float4* tf = (const float4*)(time_encoding + (ebase + row) * D_TIME);
#pragma unroll
        for (int j = 0; j < 2; j++) {
            float4 v = tf[q * 2 + j];
            unsigned h0, l0, h1, l1;
            splitpack(v.x, v.y, h0, l0);
            splitpack(v.z, v.w, h1, l1);
            const int pi = 96 + q * 4 + 2 * j;
            sSh[row * STRIDE_S + pi] = h0;     sSl[row * STRIDE_S + pi] = l0;
            sSh[row * STRIDE_S + pi + 1] = h1; sSl[row * STRIDE_S + pi + 1] = l1;
        }
    }

    float acc[2][4][4];
#pragma unroll
    for (int m = 0; m < 2; m++)
#pragma unroll
        for (int n = 0; n < 4; n++)
#pragma unroll
            for (int c = 0; c < 4; c++) acc[m][n][c] = 0.f;

    // ---- Phase 1: src_read = relu([mem|feat] @ W_read + b), K=256 ----
    for (int kc = 0; kc < 8; kc++) {
        __syncthreads();
        {   // gather + split A chunk [128 rows][32 k] -> sAh/sAl packed pairs
            const int row = tid >> 2, q = tid & 3;
            const float* base = (kc < 4)
                ? node_memory + (size_t)s_src[row] * D_MEM + kc * 32
                : node_features + (size_t)s_src[row] * D_FEAT + (kc - 4) * 32;
            const float4* b4 = (const float4*)base;
            float4 va = b4[q * 2];
            float4 vb = b4[q * 2 + 1];
            unsigned h, l;
            unsigned* ph = sAh + row * STRIDE_A + q * 4;
            unsigned* pl = sAl + row * STRIDE_A + q * 4;
            splitpack(va.x, va.y, h, l); ph[0] = h; pl[0] = l;
            splitpack(va.z, va.w, h, l); ph[1] = h; pl[1] = l;
            splitpack(vb.x, vb.y, h, l); ph[2] = h; pl[2] = l;
            splitpack(vb.z, vb.w, h, l); ph[3] = h; pl[3] = l;
        }
        {   // split W chunk [32 k][128] -> sWh/sWl [16 kpairs][128]
            const int p = tid >> 7, c = tid & 127;
            const float* Wp = W_read + kc * 32 * 128;
#pragma unroll
            for (int pp = 0; pp < 4; pp++) {
                const int kp = pp * 4 + p;
                const float x0 = Wp[(2 * kp) * 128 + c];
                const float x1 = Wp[(2 * kp + 1) * 128 + c];
                unsigned h, l;
                splitpack(x0, x1, h, l);
                sWh[kp * STRIDE_W + c] = h;
                sWl[kp * STRIDE_W + c] = l;
            }
        }
        __syncthreads();
#pragma unroll
        for (int half = 0; half < 2; half++) {
            const int kb = half * 8;
            unsigned ah[2][4], al[2][4];
#pragma unroll
            for (int mf = 0; mf < 2; mf++) {
                const int ra = r0 + mf * 16 + gid;
                ah[mf][0] = sAh[ra * STRIDE_A + kb + tig];
                ah[mf][1] = sAh[(ra + 8) * STRIDE_A + kb + tig];
                ah[mf][2] = sAh[ra * STRIDE_A + kb + tig + 4];
                ah[mf][3] = sAh[(ra + 8) * STRIDE_A + kb + tig + 4];
                al[mf][0] = sAl[ra * STRIDE_A + kb + tig];
                al[mf][1] = sAl[(ra + 8) * STRIDE_A + kb + tig];
                al[mf][2] = sAl[ra * STRIDE_A + kb + tig + 4];
                al[mf][3] = sAl[(ra + 8) * STRIDE_A + kb + tig + 4];
            }
#pragma unroll
            for (int nf = 0; nf < 4; nf++) {
                const int col = c0 + nf * 8 + gid;
                unsigned bh[2], bl[2];
                bh[0] = sWh[(kb + tig) * STRIDE_W + col];
                bh[1] = sWh[(kb + tig + 4) * STRIDE_W + col];
                bl[0] = sWl[(kb + tig) * STRIDE_W + col];
                bl[1] = sWl[(kb + tig + 4) * STRIDE_W + col];
#pragma unroll
                for (int mf = 0; mf < 2; mf++) {
                    mma_bf16(acc[mf][nf], ah[mf], bh);
                    mma_bf16(acc[mf][nf], ah[mf], bl);
                    mma_bf16(acc[mf][nf], al[mf], bh);
                }
            }
        }
    }

    // ---- Phase 1 epilogue: bias+relu -> stage kpairs [0,64) split-packed ----
#pragma unroll
    for (int mf = 0; mf < 2; mf++) {
        const int ra = r0 + mf * 16 + gid;
#pragma unroll
        for (int nf = 0; nf < 4; nf++) {
            const int col = c0 + nf * 8 + 2 * tig;
            const int pi = col >> 1;
            const float bb0 = b_read[col], bb1 = b_read[col + 1];
            unsigned h, l;
            float v0 = fmaxf(acc[mf][nf][0] + bb0, 0.f);
            float v1 = fmaxf(acc[mf][nf][1] + bb1, 0.f);
            splitpack(v0, v1, h, l);
            sSh[ra * STRIDE_S + pi] = h;
            sSl[ra * STRIDE_S + pi] = l;
            v0 = fmaxf(acc[mf][nf][2] + bb0, 0.f);
            v1 = fmaxf(acc[mf][nf][3] + bb1, 0.f);
            splitpack(v0, v1, h, l);
            sSh[(ra + 8) * STRIDE_S + pi] = h;
            sSl[(ra + 8) * STRIDE_S + pi] = l;
        }
    }

    // ---- Phase 2: msgs = relu([src_read|ef|time] @ W_msg + b), K=224 ----
#pragma unroll
    for (int m = 0; m < 2; m++)
#pragma unroll
        for (int n = 0; n < 4; n++)
#pragma unroll
            for (int c = 0; c < 4; c++) acc[m][n][c] = 0.f;

    for (int kc = 0; kc < 7; kc++) {
        __syncthreads();
        {   // split W_msg chunk
            const int p = tid >> 7, c = tid & 127;
            const float* Wp = W_msg + kc * 32 * 128;
#pragma unroll
            for (int pp = 0; pp < 4; pp++) {
                const int kp = pp * 4 + p;
                const float x0 = Wp[(2 * kp) * 128 + c];
                const float x1 = Wp[(2 * kp + 1) * 128 + c];
                unsigned h, l;
                splitpack(x0, x1, h, l);
                sWh[kp * STRIDE_W + c] = h;
                sWl[kp * STRIDE_W + c] = l;
            }
        }
        __syncthreads();
#pragma unroll
        for (int half = 0; half < 2; half++) {
            const int kbS = kc * 16 + half * 8;   // stage kpair base
            const int kbW = half * 8;
            unsigned ah[2][4], al[2][4];
#pragma unroll
            for (int mf = 0; mf < 2; mf++) {
                const int ra = r0 + mf * 16 + gid;
                ah[mf][0] = sSh[ra * STRIDE_S + kbS + tig];
                ah[mf][1] = sSh[(ra + 8) * STRIDE_S + kbS + tig];
                ah[mf][2] = sSh[ra * STRIDE_S + kbS + tig + 4];
                ah[mf][3] = sSh[(ra + 8) * STRIDE_S + kbS + tig + 4];
                al[mf][0] = sSl[ra * STRIDE_S + kbS + tig];
                al[mf][1] = sSl[(ra + 8) * STRIDE_S + kbS + tig];
                al[mf][2] = sSl[ra * STRIDE_S + kbS + tig + 4];
                al[mf][3] = sSl[(ra + 8) * STRIDE_S + kbS + tig + 4];
            }
#pragma unroll
            for (int nf = 0; nf < 4; nf++) {
                const int col = c0 + nf * 8 + gid;
                unsigned bh[2], bl[2];
                bh[0] = sWh[(kbW + tig) * STRIDE_W + col];
                bh[1] = sWh[(kbW + tig + 4) * STRIDE_W + col];
                bl[0] = sWl[(kbW + tig) * STRIDE_W + col];
                bl[1] = sWl[(kbW + tig + 4) * STRIDE_W + col];
#pragma unroll
                for (int mf = 0; mf < 2; mf++) {
                    mma_bf16(acc[mf][nf], ah[mf], bh);
                    mma_bf16(acc[mf][nf], ah[mf], bl);
                    mma_bf16(acc[mf][nf], al[mf], bh);
                }
            }
        }
    }

    // ---- Phase 2 epilogue: msgs -> msgbuf fp32 (reuse stage area) ----
    __syncthreads();
    float* msg = (float*)(su + OFF_SH);   // [128][STRIDE_M]
#pragma unroll
    for (int mf = 0; mf < 2; mf++) {
        const int ra = r0 + mf * 16 + gid;
#pragma unroll
        for (int nf = 0; nf < 4; nf++) {
            const int col = c0 + nf * 8 + 2 * tig;
            const float b0 = b_msg[col], b1 = b_msg[col + 1];
            msg[ra * STRIDE_M + col]           = fmaxf(acc[mf][nf][0] + b0, 0.f);
            msg[ra * STRIDE_M + col + 1]       = fmaxf(acc[mf][nf][1] + b1, 0.f);
            msg[(ra + 8) * STRIDE_M + col]     = fmaxf(acc[mf][nf][2] + b0, 0.f);
            msg[(ra + 8) * STRIDE_M + col + 1] = fmaxf(acc[mf][nf][3] + b1, 0.f);
        }
    }
    __syncthreads();

    // ---- run-coalesced segment-sum atomics (dest_seg globally sorted) ----
    {
        const int tx = lane;          // 4 cols per lane
        const int e0 = warp * 8;      // 16 warps x 8 edges
        int curd = s_dst[e0];
        float r[4] = {0.f, 0.f, 0.f, 0.f};
        float rl = 0.f;
#pragma unroll
        for (int i = 0; i < 8; i++) {
            const int e = e0 + i;
            const int d = s_dst[e];
            const float4 v = *(const float4*)(msg + e * STRIDE_M + tx * 4);
            if (d != curd) {
                flush_seg(curd, tx, r, rl);
                curd = d;
                r[0] = r[1] = r[2] = r[3] = 0.f;
                rl = 0.f;
            }
            r[0] += v.x; r[1] += v.y; r[2] += v.z; r[3] += v.w;
            rl += 1.f;
        }
        flush_seg(curd, tx, r, rl);
    }
}

// ---------------- dest pipeline (fp32, R1 proven; + self-zeroing) -------------
#define TILE_E 64

__device__ __forceinline__ void mma_chunk(const float* __restrict__ Asub, int strideA,
                                          const float* __restrict__ Ws,
                                          int ty, int tx, float acc[8][4]) {
#pragma unroll
    for (int k = 0; k < 32; k++) {
        const float* arow = Asub + k * strideA + ty * 8;
        float4 a0 = *(const float4*)(arow);
        float4 a1 = *(const float4*)(arow + 4);
        float4 w  = *(const float4*)(Ws + k * 128 + tx * 4);
        float av[8] = {a0.x, a0.y, a0.z, a0.w, a1.x, a1.y, a1.z, a1.w};
#pragma unroll
        for (int i = 0; i < 8; i++) {
            acc[i][0] = fmaf(av[i], w.x, acc[i][0]);
            acc[i][1] = fmaf(av[i], w.y, acc[i][1]);
            acc[i][2] = fmaf(av[i], w.z, acc[i][2]);
            acc[i][3] = fmaf(av[i], w.w, acc[i][3]);
        }
    }
}

__device__ __forceinline__ void load_w(float* Ws, const float* __restrict__ Wsrc, int tid) {
    const float4* s = (const float4*)Wsrc;
    float4* d = (float4*)Ws;
#pragma unroll
    for (int i = 0; i < 4; i++) d[tid + i * 256] = s[tid + i * 256];
}

__device__ __forceinline__ void zero_acc(float acc[8][4]) {
#pragma unroll
    for (int i = 0; i < 8; i++)
#pragma unroll
        for (int c = 0; c < 4; c++) acc[i][c] = 0.f;
}

__global__ __launch_bounds__(256) void dest_kernel(
    const float* __restrict__ node_memory, const float* __restrict__ node_features,
    const void* __restrict__ node_ids,
    const float* __restrict__ W_read, const float* __restrict__ b_read,
    const float* __restrict__ W_agg, const float* __restrict__ b_agg,
    const float* __restrict__ W_upd, const float* __restrict__ b_upd,
    const float* __restrict__ W_write, const float* __restrict__ b_write,
    float* __restrict__ out) {
    extern __shared__ float sm[];
    float* As = sm;             // [32][64]
    float* Ws = sm + 2048;      // [32][128]
    float* CT = sm + 6144;      // [256][68]
    float* DR = sm + 23552;     // [128][68]
    __shared__ int s_nid[TILE_E];

    const int tid = threadIdx.x;
    const int tx = tid & 31;
    const int ty = tid >> 5;
    const int eL = tid & 63;
    const int kq = tid >> 6;
    const int rbase = blockIdx.x * TILE_E;

    const unsigned* nw = (const unsigned*)node_ids;
    const int is64 = (nw[1] == 0u && nw[3] == 0u);

    if (tid < TILE_E) s_nid[tid] = idx_at(node_ids, rbase + tid, is64);

    float acc[8][4];
    zero_acc(acc);

    for (int kc = 0; kc < 8; kc++) {
        __syncthreads();
        {
            const float* row = (kc < 4)
                ? node_memory + (size_t)s_nid[eL] * D_MEM + kc * 32
                : node_features + (size_t)s_nid[eL] * D_FEAT + (kc - 4) * 32;
            float4 v0 = ((const float4*)row)[kq * 2];
            float4 v1 = ((const float4*)row)[kq * 2 + 1];
            int kb = kq * 8;
            As[(kb + 0) * 64 + eL] = v0.x; As[(kb + 1) * 64 + eL] = v0.y;
            As[(kb + 2) * 64 + eL] = v0.z; As[(kb + 3) * 64 + eL] = v0.w;
            As[(kb + 4) * 64 + eL] = v1.x; As[(kb + 5) * 64 + eL] = v1.y;
            As[(kb + 6) * 64 + eL] = v1.z; As[(kb + 7) * 64 + eL] = v1.w;
        }
        load_w(Ws, W_read + kc * 32 * 128, tid);
        __syncthreads();
        mma_chunk(As, 64, Ws, ty, tx, acc);
    }
    {
        float4 bb = *(const float4*)&b_read[tx * 4];
        __syncthreads();
#pragma unroll
        for (int i = 0; i < 8; i++) {
            int e = ty * 8 + i;
#pragma unroll
            for (int c = 0; c < 4; c++) {
                float bv = (c == 0) ? bb.x : (c == 1) ? bb.y : (c == 2) ? bb.z : bb.w;
                float v = fmaxf(acc[i][c] + bv, 0.f);
                CT[(tx * 4 + c) * 68 + e] = v;
                DR[(tx * 4 + c) * 68 + e] = v;
            }
        }
    }
    {
        int dg = rbase + eL;
        float inv = 1.0f / fmaxf(g_cnt[dg], 1.0f);
        const float4* srcp = (const float4*)(g_msg_sum + (size_t)dg * D_MSG + kq * 32);
#pragma unroll
        for (int j4 = 0; j4 < 8; j4++) {
            float4 v = srcp[j4];
            int kk = 128 + kq * 32 + j4 * 4;
            CT[(kk + 0) * 68 + eL] = v.x * inv; CT[(kk + 1) * 68 + eL] = v.y * inv;
            CT[(kk + 2) * 68 + eL] = v.z * inv; CT[(kk + 3) * 68 + eL] = v.w * inv;
        }
    }
    // re-zero the consumed scratch so graph replays stay deterministic
    __syncthreads();
    {
        int dg = rbase + eL;
        float4 z = {0.f, 0.f, 0.f, 0.f};
        float4* p = (float4*)(g_msg_sum + (size_t)dg * D_MSG + kq * 32);
#pragma unroll
        for (int j4 = 0; j4 < 8; j4++) p[j4] = z;
        if (kq == 0) g_cnt[dg] = 0.f;
    }

    zero_acc(acc);
    for (int kc = 0; kc < 8; kc++) {
        __syncthreads();
        load_w(Ws, W_agg + kc * 32 * 128, tid);
        __syncthreads();
        mma_chunk(CT + kc * 32 * 68, 68, Ws, ty, tx, acc);
    }
    __syncthreads();
    {
        float4 ba = *(const float4*)&b_agg[tx * 4];
#pragma unroll
        for (int i = 0; i < 8; i++) {
            int e = ty * 8 + i;
            CT[(tx * 4 + 0) * 68 + e] = fmaxf(acc[i][0] + ba.x, 0.f);
            CT[(tx * 4 + 1) * 68 + e] = fmaxf(acc[i][1] + ba.y, 0.f);
            CT[(tx * 4 + 2) * 68 + e] = fmaxf(acc[i][2] + ba.z, 0.f);
            CT[(tx * 4 + 3) * 68 + e] = fmaxf(acc[i][3] + ba.w, 0.f);
        }
#pragma unroll
        for (int j = 0; j < 32; j++) {
            int row = kq * 32 + j;
            CT[(128 + row) * 68 + eL] = DR[row * 68 + eL];
        }
    }

    zero_acc(acc);
    for (int kc = 0; kc < 8; kc++) {
        __syncthreads();
        load_w(Ws, W_upd + kc * 32 * 128, tid);
        __syncthreads();
        mma_chunk(CT + kc * 32 * 68, 68, Ws, ty, tx, acc);
    }
    __syncthreads();
    {
        float4 bu = *(const float4*)&b_upd[tx * 4];
#pragma unroll
        for (int i = 0; i < 8; i++) {
            int e = ty * 8 + i;
            DR[(tx * 4 + 0) * 68 + e] = fmaxf(acc[i][0] + bu.x, 0.f);
            DR[(tx * 4 + 1) * 68 + e] = fmaxf(acc[i][1] + bu.y, 0.f);
            DR[(tx * 4 + 2) * 68 + e] = fmaxf(acc[i][2] + bu.z, 0.f);
            DR[(tx * 4 + 3) * 68 + e] = fmaxf(acc[i][3] + bu.w, 0.f);
        }
    }

    zero_acc(acc);
    for (int kc = 0; kc < 4; kc++) {
        __syncthreads();
        load_w(Ws, W_write + kc * 32 * 128, tid);
        __syncthreads();
        mma_chunk(DR + kc * 32 * 68, 68, Ws, ty, tx, acc);
    }
    {
        float4 bw = *(const float4*)&b_write[tx * 4];
#pragma unroll
        for (int i = 0; i < 8; i++) {
            int e = ty * 8 + i;
            float4 o;
            o.x = tanhf(acc[i][0] + bw.x);
            o.y = tanhf(acc[i][1] + bw.y);
            o.z = tanhf(acc[i][2] + bw.z);
            o.w = tanhf(acc[i][3] + bw.w);
            *(float4*)(out + (size_t)s_nid[e] * D_MEM + tx * 4) = o;
        }
    }
}

// ---------------- launch ------------------------------------------------------
#define DEST_SMEM ((2048 + 4096 + 256 * 68 + 128 * 68) * 4)

extern "C" void kernel_launch(void* const* d_in, const int* in_sizes, int n_in,
                              void* d_out, int out_size) {
    const float* node_memory   = (const float*)d_in[0];
    const float* node_features = (const float*)d_in[1];
    const float* edge_features = (const float*)d_in[2];
    const float* time_encoding = (const float*)d_in[3];
    const void*  node_ids      = d_in[4];
    const void*  source_ids    = d_in[5];
    const void*  edge_ids      = d_in[6];
    const void*  dest_seg      = d_in[7];
    const float* W_read  = (const float*)d_in[8];
    const float* b_read  = (const float*)d_in[9];
    const float* W_msg   = (const float*)d_in[10];
    const float* b_msg   = (const float*)d_in[11];
    const float* W_agg   = (const float*)d_in[12];
    const float* b_agg   = (const float*)d_in[13];
    const float* W_upd   = (const float*)d_in[14];
    const float* b_upd   = (const float*)d_in[15];
    const float* W_write = (const float*)d_in[16];
    const float* b_write = (const float*)d_in[17];
    float* out = (float*)d_out;

    cudaFuncSetAttribute(edge_kernel, cudaFuncAttributeMaxDynamicSharedMemorySize, EDGE_SMEM);
    cudaFuncSetAttribute(dest_kernel, cudaFuncAttributeMaxDynamicSharedMemorySize, DEST_SMEM);

    cudaMemcpyAsync(d_out, d_in[0], (size_t)N_NODES * D_MEM * sizeof(float),
                    cudaMemcpyDeviceToDevice);

    edge_kernel<<<N_EDGE / 128, 512, EDGE_SMEM>>>(
        node_memory, node_features, edge_features, time_encoding, node_ids,
        source_ids, edge_ids, dest_seg, W_read, b_read, W_msg, b_msg);

    dest_kernel<<<N_DEST / TILE_E, 256, DEST_SMEM>>>(
        node_memory, node_features, node_ids,
        W_read, b_read, W_agg, b_agg, W_upd, b_upd, W_write, b_write, out);
}